// round 15
// baseline (speedup 1.0000x reference)
#include <cuda_runtime.h>
#include <math.h>

// Shape fixed by reference: x,y = [16, 3, 512, 512] f32
#define BATCH   16
#define HDIM    512
#define WDIM    512
#define RSTRIP  16                    // output rows per block
#define STRIPS  (HDIM / RSTRIP)       // 32
#define NBLOCKS (BATCH * STRIPS)      // 512
#define THREADS 128                   // one float4 column per thread
#define ROWSIN  (RSTRIP + 6)          // 22 streamed rows
#define ITERS   (ROWSIN / 2)          // 11 (2 rows per iteration)
#define EPSV    1e-6f

__device__ float        g_partials[NBLOCKS];
__device__ unsigned int g_count;     // zero-init at load; reset by last block

__device__ __forceinline__ void l2pf(const float* p) {
    asm volatile("prefetch.global.L2 [%0];" :: "l"(p));
}

__global__ __launch_bounds__(THREADS, 4) void charb_kernel(
    const float* __restrict__ x, const float* __restrict__ y,
    float* __restrict__ out)
{
    __shared__ float drow[2][2][520]; // [bufset][row-of-pair], halo-padded
    __shared__ float warpsum[4];
    __shared__ bool  isLast;

    const int tid  = threadIdx.x;
    const int lane = tid & 31;
    const int c0   = tid << 2;        // this thread's 4 columns

    const int blk = blockIdx.x;
    const int b   = blk / STRIPS;
    const int s   = blk % STRIPS;
    const int h0  = s * RSTRIP;
    const bool rev = (s & 1);         // serpentine: odd strips stream bottom-up
    const int rbase = rev ? (h0 + RSTRIP + 2) : (h0 - 3);
    const int rstep = rev ? -1 : 1;

    if (tid < 4) {                    // zero side halos of all 4 buffers once
        drow[0][0][tid] = 0.f; drow[0][0][516 + tid] = 0.f;
        drow[0][1][tid] = 0.f; drow[0][1][516 + tid] = 0.f;
        drow[1][0][tid] = 0.f; drow[1][0][516 + tid] = 0.f;
        drow[1][1][tid] = 0.f; drow[1][1][516 + tid] = 0.f;
    }

    const size_t plane = (size_t)HDIM * WDIM;
    const float* xb = x + (size_t)b * 3 * plane + c0;
    const float* yb = y + (size_t)b * 3 * plane + c0;

    const float4 z4 = make_float4(0.f, 0.f, 0.f, 0.f);
    // two pipelined row-load sets (rows 2k and 2k+1 of the stream)
    float4 Aa0 = z4, Aa1 = z4, Aa2 = z4, Aq0 = z4, Aq1 = z4, Aq2 = z4;
    float4 Ba0 = z4, Ba1 = z4, Ba2 = z4, Bq0 = z4, Bq1 = z4, Bq2 = z4;

    {   // prologue: load stream rows 0 and 1
        const int rA = rbase;                   // i = 0
        if (rA >= 0 && rA < HDIM) {
            const float* xp = xb + (size_t)rA * WDIM;
            const float* yp = yb + (size_t)rA * WDIM;
            Aa0 = *(const float4*)(xp);
            Aa1 = *(const float4*)(xp + plane);
            Aa2 = *(const float4*)(xp + 2 * plane);
            Aq0 = *(const float4*)(yp);
            Aq1 = *(const float4*)(yp + plane);
            Aq2 = *(const float4*)(yp + 2 * plane);
        }
        const int rB = rbase + rstep;           // i = 1
        if (rB >= 0 && rB < HDIM) {
            const float* xp = xb + (size_t)rB * WDIM;
            const float* yp = yb + (size_t)rB * WDIM;
            Ba0 = *(const float4*)(xp);
            Ba1 = *(const float4*)(xp + plane);
            Ba2 = *(const float4*)(xp + 2 * plane);
            Bq0 = *(const float4*)(yp);
            Bq1 = *(const float4*)(yp + plane);
            Bq2 = *(const float4*)(yp + 2 * plane);
        }
        // L2 prefetch rows 2,3 (one thread per 128B line)
        if ((tid & 7) == 0) {
            #pragma unroll
            for (int k = 2; k <= 3; ++k) {
                const int r = rbase + rstep * k;
                if (r >= 0 && r < HDIM) {
                    const float* xp = xb + (size_t)r * WDIM;
                    const float* yp = yb + (size_t)r * WDIM;
                    l2pf(xp); l2pf(xp + plane); l2pf(xp + 2 * plane);
                    l2pf(yp); l2pf(yp + plane); l2pf(yp + 2 * plane);
                }
            }
        }
    }

    // vertical register ring (6 previous hsum rows) + running 7-row sum
    float4 r0 = z4, r1 = z4, r2 = z4, r3 = z4, r4 = z4, r5 = z4;
    float4 vs = z4;
    float  acc = 0.f;

    #pragma unroll 1
    for (int it = 0; it < ITERS; ++it) {
        const int i0 = 2 * it;
        const int bs = it & 1;

        // channel-summed diffs for rows i0, i0+1 -> smem buffer set bs
        {
            float4 d;
            d.x = (Aa0.x - Aq0.x) + (Aa1.x - Aq1.x) + (Aa2.x - Aq2.x);
            d.y = (Aa0.y - Aq0.y) + (Aa1.y - Aq1.y) + (Aa2.y - Aq2.y);
            d.z = (Aa0.z - Aq0.z) + (Aa1.z - Aq1.z) + (Aa2.z - Aq2.z);
            d.w = (Aa0.w - Aq0.w) + (Aa1.w - Aq1.w) + (Aa2.w - Aq2.w);
            *(float4*)&drow[bs][0][4 + c0] = d;
        }
        {
            float4 d;
            d.x = (Ba0.x - Bq0.x) + (Ba1.x - Bq1.x) + (Ba2.x - Bq2.x);
            d.y = (Ba0.y - Bq0.y) + (Ba1.y - Bq1.y) + (Ba2.y - Bq2.y);
            d.z = (Ba0.z - Bq0.z) + (Ba1.z - Bq1.z) + (Ba2.z - Bq2.z);
            d.w = (Ba0.w - Bq0.w) + (Ba1.w - Bq1.w) + (Ba2.w - Bq2.w);
            *(float4*)&drow[bs][1][4 + c0] = d;
        }

        // prefetch rows i0+2, i0+3 into registers (12 LDG.128 in flight)
        {
            const int niA = i0 + 2;
            const int nrA = rbase + rstep * niA;
            const bool vA = (niA < ROWSIN) && (nrA >= 0) && (nrA < HDIM);
            Aa0 = z4; Aa1 = z4; Aa2 = z4; Aq0 = z4; Aq1 = z4; Aq2 = z4;
            if (vA) {
                const float* xp = xb + (size_t)nrA * WDIM;
                const float* yp = yb + (size_t)nrA * WDIM;
                Aa0 = *(const float4*)(xp);
                Aa1 = *(const float4*)(xp + plane);
                Aa2 = *(const float4*)(xp + 2 * plane);
                Aq0 = *(const float4*)(yp);
                Aq1 = *(const float4*)(yp + plane);
                Aq2 = *(const float4*)(yp + 2 * plane);
            }
            const int niB = i0 + 3;
            const int nrB = rbase + rstep * niB;
            const bool vB = (niB < ROWSIN) && (nrB >= 0) && (nrB < HDIM);
            Ba0 = z4; Ba1 = z4; Ba2 = z4; Bq0 = z4; Bq1 = z4; Bq2 = z4;
            if (vB) {
                const float* xp = xb + (size_t)nrB * WDIM;
                const float* yp = yb + (size_t)nrB * WDIM;
                Ba0 = *(const float4*)(xp);
                Ba1 = *(const float4*)(xp + plane);
                Ba2 = *(const float4*)(xp + 2 * plane);
                Bq0 = *(const float4*)(yp);
                Bq1 = *(const float4*)(yp + plane);
                Bq2 = *(const float4*)(yp + 2 * plane);
            }
        }

        // L2 prefetch rows i0+4, i0+5 (two iterations ahead; no registers held)
        if ((tid & 7) == 0) {
            #pragma unroll
            for (int k = 4; k <= 5; ++k) {
                const int ni = i0 + k;
                const int nr = rbase + rstep * ni;
                if (ni < ROWSIN && nr >= 0 && nr < HDIM) {
                    const float* xp = xb + (size_t)nr * WDIM;
                    const float* yp = yb + (size_t)nr * WDIM;
                    l2pf(xp); l2pf(xp + plane); l2pf(xp + 2 * plane);
                    l2pf(yp); l2pf(yp + plane); l2pf(yp + 2 * plane);
                }
            }
        }

        __syncthreads();   // publishes both rows of bufset bs; WAR gate

        // ---- row i0: horizontal 7-tap + vertical update ----
        {
            float f[12];
            *(float4*)&f[0] = *(const float4*)&drow[bs][0][c0];
            *(float4*)&f[4] = *(const float4*)&drow[bs][0][c0 + 4];
            *(float4*)&f[8] = *(const float4*)&drow[bs][0][c0 + 8];
            float4 s4;
            s4.x = ((f[1] + f[2]) + (f[3] + f[4])) + ((f[5] + f[6]) + f[7]);
            s4.y = s4.x - f[1] + f[8];
            s4.z = s4.y - f[2] + f[9];
            s4.w = s4.z - f[3] + f[10];

            vs.x += s4.x; vs.y += s4.y; vs.z += s4.z; vs.w += s4.w;
            if (i0 >= 6) {
                const float inv = 1.f / 49.f;
                const float v0 = vs.x * inv, v1 = vs.y * inv;
                const float v2 = vs.z * inv, v3 = vs.w * inv;
                acc += (sqrtf(v0 * v0 + EPSV) + sqrtf(v1 * v1 + EPSV))
                     + (sqrtf(v2 * v2 + EPSV) + sqrtf(v3 * v3 + EPSV));
                vs.x -= r0.x; vs.y -= r0.y; vs.z -= r0.z; vs.w -= r0.w;
            }
            r0 = r1; r1 = r2; r2 = r3; r3 = r4; r4 = r5; r5 = s4;
        }

        // ---- row i0+1 ----
        {
            float f[12];
            *(float4*)&f[0] = *(const float4*)&drow[bs][1][c0];
            *(float4*)&f[4] = *(const float4*)&drow[bs][1][c0 + 4];
            *(float4*)&f[8] = *(const float4*)&drow[bs][1][c0 + 8];
            float4 s4;
            s4.x = ((f[1] + f[2]) + (f[3] + f[4])) + ((f[5] + f[6]) + f[7]);
            s4.y = s4.x - f[1] + f[8];
            s4.z = s4.y - f[2] + f[9];
            s4.w = s4.z - f[3] + f[10];

            vs.x += s4.x; vs.y += s4.y; vs.z += s4.z; vs.w += s4.w;
            if (i0 + 1 >= 6) {
                const float inv = 1.f / 49.f;
                const float v0 = vs.x * inv, v1 = vs.y * inv;
                const float v2 = vs.z * inv, v3 = vs.w * inv;
                acc += (sqrtf(v0 * v0 + EPSV) + sqrtf(v1 * v1 + EPSV))
                     + (sqrtf(v2 * v2 + EPSV) + sqrtf(v3 * v3 + EPSV));
                vs.x -= r0.x; vs.y -= r0.y; vs.z -= r0.z; vs.w -= r0.w;
            }
            r0 = r1; r1 = r2; r2 = r3; r3 = r4; r4 = r5; r5 = s4;
        }
    }

    // block reduction (4 warps)
    #pragma unroll
    for (int off = 16; off; off >>= 1) acc += __shfl_xor_sync(0xffffffffu, acc, off);
    if (lane == 0) warpsum[tid >> 5] = acc;
    __syncthreads();
    if (tid < 32) {
        float v = (lane < 4) ? warpsum[lane] : 0.f;
        v += __shfl_xor_sync(0xffffffffu, v, 2);
        v += __shfl_xor_sync(0xffffffffu, v, 1);
        if (tid == 0) {
            g_partials[blk] = v;
            __threadfence();
            const unsigned int t = atomicAdd(&g_count, 1u);
            isLast = (t == NBLOCKS - 1);
        }
    }
    __syncthreads();

    // last-arriving block folds the 512 partials -> scalar (deterministic order)
    if (isLast) {
        __threadfence();
        const float4 p = *(const float4*)&g_partials[tid << 2];  // 128 x float4 = 512
        float v = (p.x + p.y) + (p.z + p.w);
        #pragma unroll
        for (int off = 16; off; off >>= 1) v += __shfl_xor_sync(0xffffffffu, v, off);
        if (lane == 0) warpsum[tid >> 5] = v;
        __syncthreads();
        if (tid < 32) {
            float v2 = (lane < 4) ? warpsum[lane] : 0.f;
            v2 += __shfl_xor_sync(0xffffffffu, v2, 2);
            v2 += __shfl_xor_sync(0xffffffffu, v2, 1);
            if (tid == 0) {
                out[0]  = v2 / (float)((size_t)BATCH * HDIM * WDIM);
                g_count = 0u;
            }
        }
    }
}

extern "C" void kernel_launch(void* const* d_in, const int* in_sizes, int n_in,
                              void* d_out, int out_size)
{
    (void)in_sizes; (void)n_in; (void)out_size;
    const float* x = (const float*)d_in[0];
    const float* y = (const float*)d_in[1];
    float* out = (float*)d_out;

    charb_kernel<<<NBLOCKS, THREADS>>>(x, y, out);
}

// round 16
// speedup vs baseline: 1.0435x; 1.0435x over previous
#include <cuda_runtime.h>
#include <math.h>

// Shape fixed by reference: x,y = [16, 3, 512, 512] f32
#define BATCH   16
#define HDIM    512
#define WDIM    512
#define RSTRIP  16                    // output rows per block
#define STRIPS  (HDIM / RSTRIP)       // 32
#define NBLOCKS (BATCH * STRIPS)      // 512
#define THREADS 128                   // one float4 column per thread
#define ROWSIN  (RSTRIP + 6)          // 22 streamed rows
#define ITERS   (ROWSIN / 2)          // 11 (2 rows per iteration)
#define EPSV    1e-6f

__device__ float        g_partials[NBLOCKS];
__device__ unsigned int g_count;     // zero-init at load; reset by last block

__global__ __launch_bounds__(THREADS, 4) void charb_kernel(
    const float* __restrict__ x, const float* __restrict__ y,
    float* __restrict__ out)
{
    __shared__ float drow[2][2][520]; // [bufset][row-of-pair], halo-padded
    __shared__ float warpsum[4];
    __shared__ bool  isLast;

    const int tid  = threadIdx.x;
    const int lane = tid & 31;
    const int c0   = tid << 2;        // this thread's 4 columns

    const int blk = blockIdx.x;
    const int b   = blk / STRIPS;
    const int s   = blk % STRIPS;
    const int h0  = s * RSTRIP;
    const bool rev = (s & 1);         // serpentine: odd strips stream bottom-up
    const int rbase = rev ? (h0 + RSTRIP + 2) : (h0 - 3);
    const int rstep = rev ? -1 : 1;

    if (tid < 4) {                    // zero side halos of all 4 buffers once
        drow[0][0][tid] = 0.f; drow[0][0][516 + tid] = 0.f;
        drow[0][1][tid] = 0.f; drow[0][1][516 + tid] = 0.f;
        drow[1][0][tid] = 0.f; drow[1][0][516 + tid] = 0.f;
        drow[1][1][tid] = 0.f; drow[1][1][516 + tid] = 0.f;
    }

    const size_t plane = (size_t)HDIM * WDIM;
    const float* xb = x + (size_t)b * 3 * plane + c0;
    const float* yb = y + (size_t)b * 3 * plane + c0;

    const float4 z4 = make_float4(0.f, 0.f, 0.f, 0.f);
    // two pipelined row-load sets (rows 2k and 2k+1 of the stream)
    float4 Aa0 = z4, Aa1 = z4, Aa2 = z4, Aq0 = z4, Aq1 = z4, Aq2 = z4;
    float4 Ba0 = z4, Ba1 = z4, Ba2 = z4, Bq0 = z4, Bq1 = z4, Bq2 = z4;

    {   // prologue: load stream rows 0 and 1
        const int rA = rbase;                   // i = 0
        if (rA >= 0 && rA < HDIM) {
            const float* xp = xb + (size_t)rA * WDIM;
            const float* yp = yb + (size_t)rA * WDIM;
            Aa0 = *(const float4*)(xp);
            Aa1 = *(const float4*)(xp + plane);
            Aa2 = *(const float4*)(xp + 2 * plane);
            Aq0 = *(const float4*)(yp);
            Aq1 = *(const float4*)(yp + plane);
            Aq2 = *(const float4*)(yp + 2 * plane);
        }
        const int rB = rbase + rstep;           // i = 1
        if (rB >= 0 && rB < HDIM) {
            const float* xp = xb + (size_t)rB * WDIM;
            const float* yp = yb + (size_t)rB * WDIM;
            Ba0 = *(const float4*)(xp);
            Ba1 = *(const float4*)(xp + plane);
            Ba2 = *(const float4*)(xp + 2 * plane);
            Bq0 = *(const float4*)(yp);
            Bq1 = *(const float4*)(yp + plane);
            Bq2 = *(const float4*)(yp + 2 * plane);
        }
    }

    // vertical register ring (6 previous hsum rows) + running 7-row sum
    float4 r0 = z4, r1 = z4, r2 = z4, r3 = z4, r4 = z4, r5 = z4;
    float4 vs = z4;
    float  acc = 0.f;

    #pragma unroll 1
    for (int it = 0; it < ITERS; ++it) {
        const int i0 = 2 * it;
        const int bs = it & 1;

        // channel-summed diffs for rows i0, i0+1 -> smem buffer set bs
        {
            float4 d;
            d.x = (Aa0.x - Aq0.x) + (Aa1.x - Aq1.x) + (Aa2.x - Aq2.x);
            d.y = (Aa0.y - Aq0.y) + (Aa1.y - Aq1.y) + (Aa2.y - Aq2.y);
            d.z = (Aa0.z - Aq0.z) + (Aa1.z - Aq1.z) + (Aa2.z - Aq2.z);
            d.w = (Aa0.w - Aq0.w) + (Aa1.w - Aq1.w) + (Aa2.w - Aq2.w);
            *(float4*)&drow[bs][0][4 + c0] = d;
        }
        {
            float4 d;
            d.x = (Ba0.x - Bq0.x) + (Ba1.x - Bq1.x) + (Ba2.x - Bq2.x);
            d.y = (Ba0.y - Bq0.y) + (Ba1.y - Bq1.y) + (Ba2.y - Bq2.y);
            d.z = (Ba0.z - Bq0.z) + (Ba1.z - Bq1.z) + (Ba2.z - Bq2.z);
            d.w = (Ba0.w - Bq0.w) + (Ba1.w - Bq1.w) + (Ba2.w - Bq2.w);
            *(float4*)&drow[bs][1][4 + c0] = d;
        }

        // prefetch rows i0+2, i0+3 (12 independent LDG.128 in flight)
        {
            const int niA = i0 + 2;
            const int nrA = rbase + rstep * niA;
            const bool vA = (niA < ROWSIN) && (nrA >= 0) && (nrA < HDIM);
            Aa0 = z4; Aa1 = z4; Aa2 = z4; Aq0 = z4; Aq1 = z4; Aq2 = z4;
            if (vA) {
                const float* xp = xb + (size_t)nrA * WDIM;
                const float* yp = yb + (size_t)nrA * WDIM;
                Aa0 = *(const float4*)(xp);
                Aa1 = *(const float4*)(xp + plane);
                Aa2 = *(const float4*)(xp + 2 * plane);
                Aq0 = *(const float4*)(yp);
                Aq1 = *(const float4*)(yp + plane);
                Aq2 = *(const float4*)(yp + 2 * plane);
            }
            const int niB = i0 + 3;
            const int nrB = rbase + rstep * niB;
            const bool vB = (niB < ROWSIN) && (nrB >= 0) && (nrB < HDIM);
            Ba0 = z4; Ba1 = z4; Ba2 = z4; Bq0 = z4; Bq1 = z4; Bq2 = z4;
            if (vB) {
                const float* xp = xb + (size_t)nrB * WDIM;
                const float* yp = yb + (size_t)nrB * WDIM;
                Ba0 = *(const float4*)(xp);
                Ba1 = *(const float4*)(xp + plane);
                Ba2 = *(const float4*)(xp + 2 * plane);
                Bq0 = *(const float4*)(yp);
                Bq1 = *(const float4*)(yp + plane);
                Bq2 = *(const float4*)(yp + 2 * plane);
            }
        }

        __syncthreads();   // publishes both rows of bufset bs; WAR gate
                           // (reads of bufset b at iter it finish before the
                           //  sync of it+1, which precedes its rewrite at it+2)

        // ---- row i0: horizontal 7-tap + vertical update ----
        {
            float f[12];
            *(float4*)&f[0] = *(const float4*)&drow[bs][0][c0];
            *(float4*)&f[4] = *(const float4*)&drow[bs][0][c0 + 4];
            *(float4*)&f[8] = *(const float4*)&drow[bs][0][c0 + 8];
            float4 s4;
            s4.x = ((f[1] + f[2]) + (f[3] + f[4])) + ((f[5] + f[6]) + f[7]);
            s4.y = s4.x - f[1] + f[8];
            s4.z = s4.y - f[2] + f[9];
            s4.w = s4.z - f[3] + f[10];

            vs.x += s4.x; vs.y += s4.y; vs.z += s4.z; vs.w += s4.w;
            if (i0 >= 6) {
                const float inv = 1.f / 49.f;
                const float v0 = vs.x * inv, v1 = vs.y * inv;
                const float v2 = vs.z * inv, v3 = vs.w * inv;
                acc += (sqrtf(v0 * v0 + EPSV) + sqrtf(v1 * v1 + EPSV))
                     + (sqrtf(v2 * v2 + EPSV) + sqrtf(v3 * v3 + EPSV));
                vs.x -= r0.x; vs.y -= r0.y; vs.z -= r0.z; vs.w -= r0.w;
            }
            r0 = r1; r1 = r2; r2 = r3; r3 = r4; r4 = r5; r5 = s4;
        }

        // ---- row i0+1 ----
        {
            float f[12];
            *(float4*)&f[0] = *(const float4*)&drow[bs][1][c0];
            *(float4*)&f[4] = *(const float4*)&drow[bs][1][c0 + 4];
            *(float4*)&f[8] = *(const float4*)&drow[bs][1][c0 + 8];
            float4 s4;
            s4.x = ((f[1] + f[2]) + (f[3] + f[4])) + ((f[5] + f[6]) + f[7]);
            s4.y = s4.x - f[1] + f[8];
            s4.z = s4.y - f[2] + f[9];
            s4.w = s4.z - f[3] + f[10];

            vs.x += s4.x; vs.y += s4.y; vs.z += s4.z; vs.w += s4.w;
            if (i0 + 1 >= 6) {
                const float inv = 1.f / 49.f;
                const float v0 = vs.x * inv, v1 = vs.y * inv;
                const float v2 = vs.z * inv, v3 = vs.w * inv;
                acc += (sqrtf(v0 * v0 + EPSV) + sqrtf(v1 * v1 + EPSV))
                     + (sqrtf(v2 * v2 + EPSV) + sqrtf(v3 * v3 + EPSV));
                vs.x -= r0.x; vs.y -= r0.y; vs.z -= r0.z; vs.w -= r0.w;
            }
            r0 = r1; r1 = r2; r2 = r3; r3 = r4; r4 = r5; r5 = s4;
        }
    }

    // block reduction (4 warps)
    #pragma unroll
    for (int off = 16; off; off >>= 1) acc += __shfl_xor_sync(0xffffffffu, acc, off);
    if (lane == 0) warpsum[tid >> 5] = acc;
    __syncthreads();
    if (tid < 32) {
        float v = (lane < 4) ? warpsum[lane] : 0.f;
        v += __shfl_xor_sync(0xffffffffu, v, 2);
        v += __shfl_xor_sync(0xffffffffu, v, 1);
        if (tid == 0) {
            g_partials[blk] = v;
            __threadfence();
            const unsigned int t = atomicAdd(&g_count, 1u);
            isLast = (t == NBLOCKS - 1);
        }
    }
    __syncthreads();

    // last-arriving block folds the 512 partials -> scalar (deterministic order)
    if (isLast) {
        __threadfence();
        const float4 p = *(const float4*)&g_partials[tid << 2];  // 128 x float4 = 512
        float v = (p.x + p.y) + (p.z + p.w);
        #pragma unroll
        for (int off = 16; off; off >>= 1) v += __shfl_xor_sync(0xffffffffu, v, off);
        if (lane == 0) warpsum[tid >> 5] = v;
        __syncthreads();
        if (tid < 32) {
            float v2 = (lane < 4) ? warpsum[lane] : 0.f;
            v2 += __shfl_xor_sync(0xffffffffu, v2, 2);
            v2 += __shfl_xor_sync(0xffffffffu, v2, 1);
            if (tid == 0) {
                out[0]  = v2 / (float)((size_t)BATCH * HDIM * WDIM);
                g_count = 0u;
            }
        }
    }
}

extern "C" void kernel_launch(void* const* d_in, const int* in_sizes, int n_in,
                              void* d_out, int out_size)
{
    (void)in_sizes; (void)n_in; (void)out_size;
    const float* x = (const float*)d_in[0];
    const float* y = (const float*)d_in[1];
    float* out = (float*)d_out;

    charb_kernel<<<NBLOCKS, THREADS>>>(x, y, out);
}